// round 16
// baseline (speedup 1.0000x reference)
#include <cuda_runtime.h>
#include <cstdint>

// ----------------------------------------------------------------------------
// Fused sparse conv, TF32 m16n8k8, cp.async double-buffered pipeline.
//  - B fragments hoisted to REGISTERS for the whole kernel (tile-invariant):
//    zero B-LDS in the mainloop, no W smem at all.
//  - k-pair permute (MMA k-slots (tig,tig+4) ↦ real k (2tig,2tig+1)) makes
//    each A fragment one aligned LDS.64 (B's k-rows re-paired in wprep).
//  - channel permute -> red.v4 scatter straight from accumulators.
// ----------------------------------------------------------------------------

constexpr int CIN   = 32;
constexpr int CMID  = 64;
constexpr int COUT  = 32;
constexpr int MAXK  = 27;
constexpr int MAXP  = 400000;
constexpr int MAXN  = 200192;
constexpr int PT1   = 128;      // pairs per tile, layer 1
constexpr int PT2   = 64;       // pairs per tile, layer 2

constexpr int SX1R = 36;        // raw x row stride (floats); %32=4, 16B-mult
constexpr int SX2R = 68;
constexpr int SWQ  = 68;        // W fragment-row stride (float2) in gmem
constexpr int WK1  = 16 * SWQ * 2;   // 2176 floats per k
constexpr int WK2  = 32 * SWQ * 2;   // 4352 floats per k

constexpr int POOL1F = 2 * PT1 * SX1R;   // 9216 f  = 36.9 KB
constexpr int POOL2F = 2 * PT2 * SX2R;   // 8704 f  = 34.8 KB

__device__ float g_h[(size_t)MAXN * CMID];
__device__ uint2 g_pairs[(size_t)MAXK * MAXP];
__device__ int   g_cnt[MAXK];
__device__ float g_wq1[(size_t)MAXK * WK1];
__device__ float g_wq2[(size_t)MAXK * WK2];

static __device__ __forceinline__ unsigned f2tf(float x) {
    unsigned r; asm("cvt.rna.tf32.f32 %0, %1;" : "=r"(r) : "f"(x)); return r;
}
static __device__ __forceinline__ float f2tf_f(float x) {
    return __uint_as_float(f2tf(x));
}
static __device__ __forceinline__ void mma_tf32(
    float4& c, unsigned a0, unsigned a1, unsigned a2, unsigned a3,
    unsigned b0, unsigned b1)
{
    asm volatile(
        "mma.sync.aligned.m16n8k8.row.col.f32.tf32.tf32.f32 "
        "{%0,%1,%2,%3}, {%4,%5,%6,%7}, {%8,%9}, {%0,%1,%2,%3};"
        : "+f"(c.x), "+f"(c.y), "+f"(c.z), "+f"(c.w)
        : "r"(a0), "r"(a1), "r"(a2), "r"(a3), "r"(b0), "r"(b1));
}
static __device__ __forceinline__ void red_add_v4(float* p, float4 v) {
    asm volatile("red.global.add.v4.f32 [%0], {%1, %2, %3, %4};"
                 :: "l"(p), "f"(v.x), "f"(v.y), "f"(v.z), "f"(v.w) : "memory");
}
static __device__ __forceinline__ void cp_async16(float* smem, const float* g) {
    unsigned s = (unsigned)__cvta_generic_to_shared(smem);
    asm volatile("cp.async.ca.shared.global [%0], [%1], 16;" :: "r"(s), "l"(g));
}
#define CP_COMMIT() asm volatile("cp.async.commit_group;" ::: "memory")
#define CP_WAIT0()  asm volatile("cp.async.wait_group 0;"  ::: "memory")

// ---------------------------------------------------------------------------
__global__ void zero_kernel(float4* __restrict__ out, int n_out4, int n_h4) {
    int i = blockIdx.x * blockDim.x + threadIdx.x;
    float4 z = make_float4(0.f, 0.f, 0.f, 0.f);
    if (i < n_out4) out[i] = z;
    if (i < n_h4) reinterpret_cast<float4*>(g_h)[i] = z;
    if (i < MAXK) g_cnt[i] = 0;
}

// ---------------------------------------------------------------------------
// W permute: k-rows fragment-ordered with PAIRED k (tig=j>>1, half=j&1 so
// .x = real k 2tig, .y = real k 2tig+1) + channel perm for red.v4 scatter.
// ---------------------------------------------------------------------------
__global__ void wprep_kernel(const float* __restrict__ W_in,
                             const float* __restrict__ W_out, int K) {
    int i = blockIdx.x * blockDim.x + threadIdx.x;
    const int tot = K * CIN * CMID;
    if (i < tot) {   // layer 1
        int k = i / (CIN * CMID), r = i % (CIN * CMID);
        int c = r >> 6, d = r & 63;
        int ks = c >> 3, j = c & 7, tig = j >> 1, half = j & 1;
        int dc = d & 31, dhi = d & ~31;
        int tg = (dc & 15) >> 2, rem = dc & 3, sub = rem >> 1, b = rem & 1;
        int slot = (2 * ((dc >> 4) & 1) + sub) * 8 + 2 * tg + b;
        g_wq1[(size_t)k * WK1 + ((ks * 4 + tig) * SWQ + (dhi | slot)) * 2 + half] =
            f2tf_f(W_in[i]);
    }
    if (i < tot) {   // layer 2
        int k = i / (CMID * COUT), r = i % (CMID * COUT);
        int c = r >> 5, d = r & 31;
        int ks = c >> 3, j = c & 7, tig = j >> 1, half = j & 1;
        int dc = d & 15, dhi = d & ~15;
        int tg = dc >> 2, rem = dc & 3, sub = rem >> 1, b = rem & 1;
        int slot = sub * 8 + 2 * tg + b;
        g_wq2[(size_t)k * WK2 + ((ks * 4 + tig) * SWQ + (dhi | slot)) * 2 + half] =
            f2tf_f(W_out[i]);
    }
}

// ---------------------------------------------------------------------------
__global__ __launch_bounds__(256) void compact_kernel(
    const int* __restrict__ in_idx, const int* __restrict__ out_idx,
    const float* __restrict__ mask, int P)
{
    const int k = blockIdx.y;
    const int p = blockIdx.x * blockDim.x + threadIdx.x;
    bool v = false; int vin = 0, vout = 0;
    if (p < P) {
        size_t o = (size_t)k * P + p;
        v = mask[o] > 0.5f;
        if (v) { vin = in_idx[o]; vout = out_idx[o]; }
    }
    unsigned b = __ballot_sync(0xffffffffu, v);
    int cnt = __popc(b);
    if (cnt == 0) return;
    const int lane = threadIdx.x & 31;
    const int leader = __ffs(b) - 1;
    int base = 0;
    if (lane == leader) base = atomicAdd(&g_cnt[k], cnt);
    base = __shfl_sync(0xffffffffu, base, leader);
    if (v) {
        int off = __popc(b & ((1u << lane) - 1u));
        g_pairs[(size_t)k * MAXP + base + off] =
            make_uint2((unsigned)vin, (unsigned)vout);
    }
}

// ---------------------------------------------------------------------------
// Fused layer 1 (pipelined, B-in-regs): g_h += feats[vin] @ W_in[k]
// Warp tile MT=2 (rows 32*(w&3)), NT=4 (cols 32*(w>>2)). K=32.
// ---------------------------------------------------------------------------
__global__ __launch_bounds__(256, 2) void fused1_kernel(
    const float* __restrict__ feats)
{
    const int k   = blockIdx.y;
    const int cnt = g_cnt[k];
    if (blockIdx.x * PT1 >= cnt) return;
    const int t    = threadIdx.x;
    const int lane = t & 31;
    const int wrp  = t >> 5;

    extern __shared__ float pool[];
    float* xb = pool;                                   // [2][PT1][SX1R]
    __shared__ uint2 sp[2][PT1];

    const size_t kpair = (size_t)k * MAXP;
    const int gid = lane >> 2, tig = lane & 3;
    const int rbase = 32 * (wrp & 3);
    const int cbase = 32 * (wrp >> 2);

    // B fragments for the whole kernel: 4 ks x 4 nt, one float2 each.
    float2 bf[4][4];
    {
        const float2* wq = reinterpret_cast<const float2*>(g_wq1 + (size_t)k * WK1)
                           + tig * SWQ;
#pragma unroll
        for (int ks = 0; ks < 4; ks++)
#pragma unroll
            for (int nt = 0; nt < 4; nt++)
                bf[ks][nt] = wq[ks * 4 * SWQ + cbase + nt * 8 + gid];
    }

    auto prefetch = [&](int tile, int b) {
        const int base = tile * PT1;
        const int r = t >> 1, half = t & 1;
        uint2 pr = (base + r < cnt) ? g_pairs[kpair + base + r]
                                    : make_uint2(0u, 0u);
        if (half == 0) sp[b][r] = pr;
        const float* src = feats + (size_t)pr.x * CIN + half * 16;
        float* dst = xb + ((size_t)b * PT1 + r) * SX1R + half * 16;
        cp_async16(dst,      src);
        cp_async16(dst + 4,  src + 4);
        cp_async16(dst + 8,  src + 8);
        cp_async16(dst + 12, src + 12);
    };

    prefetch(blockIdx.x, 0);
    CP_COMMIT();

    int buf = 0;
    for (int tile = blockIdx.x; tile * PT1 < cnt; tile += gridDim.x, buf ^= 1) {
        const int nv = min(PT1, cnt - tile * PT1);
        CP_WAIT0();
        __syncthreads();

        {
            int ntile = tile + gridDim.x;
            if (ntile * PT1 < cnt) prefetch(ntile, buf ^ 1);
            CP_COMMIT();
        }

        const float* xr = xb + (size_t)buf * PT1 * SX1R;
        float4 acc[2][4];
#pragma unroll
        for (int mt = 0; mt < 2; mt++)
#pragma unroll
            for (int nt = 0; nt < 4; nt++) acc[mt][nt] = make_float4(0.f, 0.f, 0.f, 0.f);

#pragma unroll
        for (int ks = 0; ks < 4; ks++) {
            // A fragment: k-slots (tig, tig+4) = real k (2tig, 2tig+1) -> LDS.64
            const float2* xrr = reinterpret_cast<const float2*>(
                xr + (rbase + gid) * SX1R + ks * 8) + tig;
            float2 q0 = xrr[0];                 // row r0
            float2 q1 = xrr[(8  * SX1R) / 2];   // row r0+8
            float2 q2 = xrr[(16 * SX1R) / 2];   // row r0+16
            float2 q3 = xrr[(24 * SX1R) / 2];   // row r0+24
            unsigned a00 = f2tf(q0.x), a02 = f2tf(q0.y);
            unsigned a01 = f2tf(q1.x), a03 = f2tf(q1.y);
            unsigned a10 = f2tf(q2.x), a12 = f2tf(q2.y);
            unsigned a11 = f2tf(q3.x), a13 = f2tf(q3.y);
#pragma unroll
            for (int nt = 0; nt < 4; nt++) {
                unsigned b0 = __float_as_uint(bf[ks][nt].x);
                unsigned b1 = __float_as_uint(bf[ks][nt].y);
                mma_tf32(acc[0][nt], a00, a01, a02, a03, b0, b1);
                mma_tf32(acc[1][nt], a10, a11, a12, a13, b0, b1);
            }
        }

#pragma unroll
        for (int mt = 0; mt < 2; mt++) {
            const int r0 = rbase + mt * 16 + gid;
#pragma unroll
            for (int q = 0; q < 2; q++) {
                const int cc = cbase + 16 * q + 4 * tig;
                if (r0 < nv)
                    red_add_v4(g_h + (size_t)sp[buf][r0].y * CMID + cc,
                               make_float4(acc[mt][2 * q].x,     acc[mt][2 * q].y,
                                           acc[mt][2 * q + 1].x, acc[mt][2 * q + 1].y));
                if (r0 + 8 < nv)
                    red_add_v4(g_h + (size_t)sp[buf][r0 + 8].y * CMID + cc,
                               make_float4(acc[mt][2 * q].z,     acc[mt][2 * q].w,
                                           acc[mt][2 * q + 1].z, acc[mt][2 * q + 1].w));
            }
        }
    }
}

// ---------------------------------------------------------------------------
// Fused layer 2 (pipelined, B-in-regs, PT=64): out += relu(h[vin]) @ W_out[k]
// Warp tile MT=1 (rows 16*(w&3)), NT=2 (cols 16*(w>>2)). K=64 (8 ks).
// ---------------------------------------------------------------------------
__global__ __launch_bounds__(256, 2) void fused2_kernel(float* __restrict__ out)
{
    const int k   = blockIdx.y;
    const int cnt = g_cnt[k];
    if (blockIdx.x * PT2 >= cnt) return;
    const int t    = threadIdx.x;
    const int lane = t & 31;
    const int wrp  = t >> 5;

    extern __shared__ float pool[];
    float* xb = pool;                                   // [2][PT2][SX2R]
    __shared__ uint2 sp[2][PT2];

    const size_t kpair = (size_t)k * MAXP;
    const int gid = lane >> 2, tig = lane & 3;
    const int rbase = 16 * (wrp & 3);
    const int cbase = 16 * (wrp >> 2);

    // B fragments: 8 ks x 2 nt.
    float2 bf[8][2];
    {
        const float2* wq = reinterpret_cast<const float2*>(g_wq2 + (size_t)k * WK2)
                           + tig * SWQ;
#pragma unroll
        for (int ks = 0; ks < 8; ks++)
#pragma unroll
            for (int nt = 0; nt < 2; nt++)
                bf[ks][nt] = wq[ks * 4 * SWQ + cbase + nt * 8 + gid];
    }

    auto prefetch = [&](int tile, int b) {
        const int base = tile * PT2;
        const int r = t >> 2, q = t & 3;
        uint2 pr = (base + r < cnt) ? g_pairs[kpair + base + r]
                                    : make_uint2(0u, 0u);
        if (q == 0) sp[b][r] = pr;
        const float* src = g_h + (size_t)pr.x * CMID + q * 16;
        float* dst = xb + ((size_t)b * PT2 + r) * SX2R + q * 16;
        cp_async16(dst,      src);
        cp_async16(dst + 4,  src + 4);
        cp_async16(dst + 8,  src + 8);
        cp_async16(dst + 12, src + 12);
    };

    prefetch(blockIdx.x, 0);
    CP_COMMIT();

    int buf = 0;
    for (int tile = blockIdx.x; tile * PT2 < cnt; tile += gridDim.x, buf ^= 1) {
        const int nv = min(PT2, cnt - tile * PT2);
        CP_WAIT0();
        __syncthreads();

        {
            int ntile = tile + gridDim.x;
            if (ntile * PT2 < cnt) prefetch(ntile, buf ^ 1);
            CP_COMMIT();
        }

        const float* xr = xb + (size_t)buf * PT2 * SX2R;
        float4 acc[2];
        acc[0] = make_float4(0.f, 0.f, 0.f, 0.f);
        acc[1] = make_float4(0.f, 0.f, 0.f, 0.f);

#pragma unroll
        for (int ks = 0; ks < 8; ks++) {
            const float2* xrr = reinterpret_cast<const float2*>(
                xr + (rbase + gid) * SX2R + ks * 8) + tig;
            float2 q0 = xrr[0];
            float2 q1 = xrr[(8 * SX2R) / 2];
            unsigned a0 = f2tf(fmaxf(q0.x, 0.f));
            unsigned a2 = f2tf(fmaxf(q0.y, 0.f));
            unsigned a1 = f2tf(fmaxf(q1.x, 0.f));
            unsigned a3 = f2tf(fmaxf(q1.y, 0.f));
#pragma unroll
            for (int nt = 0; nt < 2; nt++)
                mma_tf32(acc[nt], a0, a1, a2, a3,
                         __float_as_uint(bf[ks][nt].x),
                         __float_as_uint(bf[ks][nt].y));
        }

        {
            const int r0 = rbase + gid;
            const int cc = cbase + 4 * tig;
            if (r0 < nv)
                red_add_v4(out + (size_t)sp[buf][r0].y * COUT + cc,
                           make_float4(acc[0].x, acc[0].y, acc[1].x, acc[1].y));
            if (r0 + 8 < nv)
                red_add_v4(out + (size_t)sp[buf][r0 + 8].y * COUT + cc,
                           make_float4(acc[0].z, acc[0].w, acc[1].z, acc[1].w));
        }
    }
}

// ---------------------------------------------------------------------------
// Inputs: feats f32[N,32], nbr_in_idx i32[K,P], nbr_out_idx i32[K,P],
// nbr_mask f32[K,P], W_in f32[K,32,64], W_out f32[K,64,32]. Output f32[N,32].
// ---------------------------------------------------------------------------
extern "C" void kernel_launch(void* const* d_in, const int* in_sizes, int n_in,
                              void* d_out, int out_size) {
    const float* feats   = (const float*)d_in[0];
    const int*   in_idx  = (const int*)  d_in[1];
    const int*   out_idx = (const int*)  d_in[2];
    const float* mask    = (const float*)d_in[3];
    const float* W_in    = (const float*)d_in[4];
    const float* W_out   = (const float*)d_in[5];
    float*       out     = (float*)      d_out;

    const int N = in_sizes[0] / CIN;
    const int K = in_sizes[4] / (CIN * CMID);
    const int P = in_sizes[3] / K;

    const int smem1 = POOL1F * (int)sizeof(float);   // ~36.9 KB
    const int smem2 = POOL2F * (int)sizeof(float);   // ~34.8 KB
    cudaFuncSetAttribute(fused1_kernel,
        cudaFuncAttributeMaxDynamicSharedMemorySize, smem1);
    cudaFuncSetAttribute(fused2_kernel,
        cudaFuncAttributeMaxDynamicSharedMemorySize, smem2);

    const int n_out4 = N * COUT / 4;
    const int n_h4   = N * CMID / 4;
    const int nmax   = (n_out4 > n_h4) ? n_out4 : n_h4;
    zero_kernel<<<(nmax + 255) / 256, 256>>>((float4*)out, n_out4, n_h4);

    const int wtot = K * CIN * CMID;
    wprep_kernel<<<(wtot + 255) / 256, 256>>>(W_in, W_out, K);

    dim3 gc((P + 255) / 256, K);
    compact_kernel<<<gc, 256>>>(in_idx, out_idx, mask, P);

    const int gx1 = (((P + PT1 - 1) / PT1) + 3) / 4;
    const int gx2 = (((P + PT2 - 1) / PT2) + 7) / 8;
    fused1_kernel<<<dim3(gx1, K), 256, smem1>>>(feats);
    fused2_kernel<<<dim3(gx2, K), 256, smem2>>>(out);
}